// round 16
// baseline (speedup 1.0000x reference)
#include <cuda_runtime.h>
#include <cuda_bf16.h>
#include <cstdint>

#define IN_F 128
#define OUT_F 64
#define MAX_N 100000
#define MAX_E 1600000
#define ALPHAF 10.0f

// Scratch (allocation-free rule: __device__ globals)
__device__ int      g_cnt[MAX_N];        // per-dst in-degree counts
__device__ int      g_rowstart[MAX_N];   // CSR row offsets
__device__ int      g_cursor[MAX_N];     // scatter cursors
__device__ float    g_deg[MAX_N];        // sum of incoming edge weights
__device__ unsigned g_h16[(size_t)MAX_N * (OUT_F / 2)];  // h rows in bf16x2 words
__device__ unsigned g_epack[MAX_E];      // packed edge: src | (etype<<17)
// scan state: per-block aggregate + publish flag
__device__ volatile int g_scanflag[64];
__device__ volatile int g_scanagg[64];

// ---------------------------------------------------------------------------
// K1: zero counters + deg + scan flags
// ---------------------------------------------------------------------------
__global__ void zero_kernel(int n) {
    int i = blockIdx.x * blockDim.x + threadIdx.x;
    if (i < n) { g_cnt[i] = 0; g_deg[i] = 0.0f; }
    if (blockIdx.x == 0 && threadIdx.x < 64) g_scanflag[threadIdx.x] = 0;
}

// ---------------------------------------------------------------------------
// K2: histogram of dst + fused deg accumulation. 4 edges/thread (MLP=4).
// atomicAdd returns UNUSED -> REDG (no round-trip).
// ---------------------------------------------------------------------------
__global__ void hist_kernel(const int* __restrict__ dst,
                            const int* __restrict__ efeat,
                            const float* __restrict__ edge_weight,
                            int E) {
    int e = (blockIdx.x * blockDim.x + threadIdx.x) * 4;
    if (e + 3 < E) {
        int4 d4 = *reinterpret_cast<const int4*>(dst + e);
        int4 t4 = *reinterpret_cast<const int4*>(efeat + e);
        float w0 = __ldg(&edge_weight[t4.x - 1]) * ALPHAF;
        float w1 = __ldg(&edge_weight[t4.y - 1]) * ALPHAF;
        float w2 = __ldg(&edge_weight[t4.z - 1]) * ALPHAF;
        float w3 = __ldg(&edge_weight[t4.w - 1]) * ALPHAF;
        w0 = (w0 > 0.0f) ? w0 : 0.01f * w0;
        w1 = (w1 > 0.0f) ? w1 : 0.01f * w1;
        w2 = (w2 > 0.0f) ? w2 : 0.01f * w2;
        w3 = (w3 > 0.0f) ? w3 : 0.01f * w3;
        atomicAdd(&g_cnt[d4.x], 1);
        atomicAdd(&g_cnt[d4.y], 1);
        atomicAdd(&g_cnt[d4.z], 1);
        atomicAdd(&g_cnt[d4.w], 1);
        atomicAdd(&g_deg[d4.x], w0);
        atomicAdd(&g_deg[d4.y], w1);
        atomicAdd(&g_deg[d4.z], w2);
        atomicAdd(&g_deg[d4.w], w3);
    } else {
        for (; e < E; e++) {
            int d = dst[e];
            float w = __ldg(&edge_weight[efeat[e] - 1]) * ALPHAF;
            w = (w > 0.0f) ? w : 0.01f * w;
            atomicAdd(&g_cnt[d], 1);
            atomicAdd(&g_deg[d], w);
        }
    }
}

// ---------------------------------------------------------------------------
// K3: single-pass exclusive scan (parallel aggregate lookback)
// ---------------------------------------------------------------------------
__global__ __launch_bounds__(256) void scan_kernel(int n) {
    __shared__ int s[256];
    __shared__ int s_off;
    const int tid = threadIdx.x;
    const int b = blockIdx.x;
    const int base = b * 2048 + tid * 8;

    int v[8];
    int tsum = 0;
    #pragma unroll
    for (int j = 0; j < 8; j++) {
        int idx = base + j;
        int c = (idx < n) ? g_cnt[idx] : 0;
        v[j] = tsum;
        tsum += c;
    }
    s[tid] = tsum;
    __syncthreads();
    #pragma unroll
    for (int off = 1; off < 256; off <<= 1) {
        int t = 0;
        if (tid >= off) t = s[tid - off];
        __syncthreads();
        if (tid >= off) s[tid] += t;
        __syncthreads();
    }
    int texcl = s[tid] - tsum;
    int total = s[255];

    if (tid == 0) {
        s_off = 0;
        g_scanagg[b] = total;
        __threadfence();
        g_scanflag[b] = 1;
    }
    __syncthreads();

    if (tid < 32 && b > 0) {
        int run = 0;
        for (int base2 = 0; base2 < b; base2 += 32) {
            int p = base2 + tid;
            int val = 0;
            if (p < b) {
                while (g_scanflag[p] == 0) { }
                __threadfence();
                val = g_scanagg[p];
            }
            #pragma unroll
            for (int o = 16; o; o >>= 1)
                val += __shfl_down_sync(0xffffffffu, val, o);
            if (tid == 0) run += val;
        }
        if (tid == 0) s_off = run;
    }
    __syncthreads();
    int off = s_off;

    #pragma unroll
    for (int j = 0; j < 8; j++) {
        int idx = base + j;
        if (idx < n) {
            int r = off + texcl + v[j];
            g_rowstart[idx] = r;
            g_cursor[idx] = r;
        }
    }
}

// ---------------------------------------------------------------------------
// K4: scatter packed edges into CSR slots (cursor atomic). 4 edges/thread
// via int4 loads -> 4 independent ATOMG chains in flight.
// ---------------------------------------------------------------------------
__global__ void scatter_kernel(const int* __restrict__ src,
                               const int* __restrict__ dst,
                               const int* __restrict__ efeat,
                               int E) {
    int e = (blockIdx.x * blockDim.x + threadIdx.x) * 4;
    if (e + 3 < E) {
        int4 s4 = *reinterpret_cast<const int4*>(src + e);
        int4 d4 = *reinterpret_cast<const int4*>(dst + e);
        int4 t4 = *reinterpret_cast<const int4*>(efeat + e);
        int p0 = atomicAdd(&g_cursor[d4.x], 1);
        int p1 = atomicAdd(&g_cursor[d4.y], 1);
        int p2 = atomicAdd(&g_cursor[d4.z], 1);
        int p3 = atomicAdd(&g_cursor[d4.w], 1);
        g_epack[p0] = (unsigned)s4.x | ((unsigned)(t4.x - 1) << 17);
        g_epack[p1] = (unsigned)s4.y | ((unsigned)(t4.y - 1) << 17);
        g_epack[p2] = (unsigned)s4.z | ((unsigned)(t4.z - 1) << 17);
        g_epack[p3] = (unsigned)s4.w | ((unsigned)(t4.w - 1) << 17);
    } else {
        for (; e < E; e++) {
            int d = dst[e];
            int p = atomicAdd(&g_cursor[d], 1);
            g_epack[p] = (unsigned)src[e] | ((unsigned)(efeat[e] - 1) << 17);
        }
    }
}

// ---------------------------------------------------------------------------
// K5: TF32 tensor-core GEMM with 3xTF32 compensation (~fp32 accuracy).
// ---------------------------------------------------------------------------
#define SA_STRIDE 132   // 64 rows
#define SB_STRIDE 72    // 128 rows

__device__ __forceinline__ unsigned f2tf32(float f) {
    unsigned r;
    asm("cvt.rna.tf32.f32 %0, %1;" : "=r"(r) : "f"(f));
    return r;
}

#define MMA_TF32(c, a0, a1, a2, a3, b0, b1)                                   \
    asm volatile("mma.sync.aligned.m16n8k8.row.col.f32.tf32.tf32.f32 "        \
                 "{%0,%1,%2,%3}, {%4,%5,%6,%7}, {%8,%9}, {%0,%1,%2,%3};"      \
                 : "+f"((c)[0]), "+f"((c)[1]), "+f"((c)[2]), "+f"((c)[3])     \
                 : "r"(a0), "r"(a1), "r"(a2), "r"(a3), "r"(b0), "r"(b1))

__global__ __launch_bounds__(256) void gemm_kernel(
    const float* __restrict__ feat,
    const float* __restrict__ weight,
    const float* __restrict__ bias,
    float* __restrict__ out,
    int n)
{
    __shared__ float sA[64 * SA_STRIDE];
    __shared__ float sB[IN_F * SB_STRIDE];

    const int tid = threadIdx.x;
    const int rowBase = blockIdx.x * 64;

    #pragma unroll
    for (int it = 0; it < 8; it++) {
        int idx = tid + it * 256;
        int r = idx >> 5;
        int c4 = idx & 31;
        float4 v = make_float4(0.f, 0.f, 0.f, 0.f);
        int gr = rowBase + r;
        if (gr < n)
            v = reinterpret_cast<const float4*>(feat)[(size_t)gr * (IN_F / 4) + c4];
        *reinterpret_cast<float4*>(&sA[r * SA_STRIDE + c4 * 4]) = v;
    }
    #pragma unroll
    for (int it = 0; it < 8; it++) {
        int idx = tid + it * 256;
        int r = idx >> 4;
        int c4 = idx & 15;
        float4 v = reinterpret_cast<const float4*>(weight)[(size_t)r * (OUT_F / 4) + c4];
        *reinterpret_cast<float4*>(&sB[r * SB_STRIDE + c4 * 4]) = v;
    }
    __syncthreads();

    const int wid = tid >> 5;
    const int lane = tid & 31;
    const int g = lane >> 2;
    const int t = lane & 3;
    const int m0 = (wid & 3) * 16;
    const int n0 = (wid >> 2) * 32;

    float c[4][4];
    #pragma unroll
    for (int nt = 0; nt < 4; nt++)
        #pragma unroll
        for (int j = 0; j < 4; j++) c[nt][j] = 0.0f;

    #pragma unroll
    for (int ks = 0; ks < IN_F / 8; ks++) {
        int k0 = ks * 8;
        float af0 = sA[(m0 + g)     * SA_STRIDE + k0 + t];
        float af1 = sA[(m0 + g + 8) * SA_STRIDE + k0 + t];
        float af2 = sA[(m0 + g)     * SA_STRIDE + k0 + t + 4];
        float af3 = sA[(m0 + g + 8) * SA_STRIDE + k0 + t + 4];
        unsigned ah0 = f2tf32(af0), ah1 = f2tf32(af1), ah2 = f2tf32(af2), ah3 = f2tf32(af3);
        unsigned al0 = f2tf32(af0 - __uint_as_float(ah0));
        unsigned al1 = f2tf32(af1 - __uint_as_float(ah1));
        unsigned al2 = f2tf32(af2 - __uint_as_float(ah2));
        unsigned al3 = f2tf32(af3 - __uint_as_float(ah3));

        #pragma unroll
        for (int nt = 0; nt < 4; nt++) {
            int nc = n0 + nt * 8 + g;
            float bf0 = sB[(k0 + t)     * SB_STRIDE + nc];
            float bf1 = sB[(k0 + t + 4) * SB_STRIDE + nc];
            unsigned bh0 = f2tf32(bf0), bh1 = f2tf32(bf1);
            unsigned bl0 = f2tf32(bf0 - __uint_as_float(bh0));
            unsigned bl1 = f2tf32(bf1 - __uint_as_float(bh1));
            MMA_TF32(c[nt], ah0, ah1, ah2, ah3, bh0, bh1);
            MMA_TF32(c[nt], al0, al1, al2, al3, bh0, bh1);
            MMA_TF32(c[nt], ah0, ah1, ah2, ah3, bl0, bl1);
        }
    }

    #pragma unroll
    for (int half = 0; half < 2; half++) {
        int gr = rowBase + m0 + g + half * 8;
        if (gr < n) {
            float d = g_deg[gr];
            float norm = 1.0f / fmaxf(d, 1.0f);
            #pragma unroll
            for (int nt = 0; nt < 4; nt++) {
                int col = n0 + nt * 8 + 2 * t;
                float cx = c[nt][half * 2 + 0];
                float cy = c[nt][half * 2 + 1];
                float2 bi = *reinterpret_cast<const float2*>(bias + col);
                float2 o = make_float2(cx + bi.x, cy + bi.y);
                *reinterpret_cast<float2*>(out + (size_t)gr * OUT_F + col) = o;
                __nv_bfloat162 p = __floats2bfloat162_rn(cx * norm, cy * norm);
                g_h16[(size_t)gr * (OUT_F / 2) + (col >> 1)] = *reinterpret_cast<unsigned*>(&p);
            }
        }
    }
}

// ---------------------------------------------------------------------------
// K6: pull-gather. 8 threads per dst node; uint4 (16B) per lane; unroll x4
// ---------------------------------------------------------------------------
__global__ __launch_bounds__(256) void gather_kernel(
    float* __restrict__ out,
    const float* __restrict__ edge_weight,
    int n)
{
    __shared__ float s_wl[8];
    if (threadIdx.x < 8) {
        float w = edge_weight[threadIdx.x] * ALPHAF;
        s_wl[threadIdx.x] = (w > 0.0f) ? w : 0.01f * w;
    }
    __syncthreads();

    int node = blockIdx.x * 32 + (threadIdx.x >> 3);
    int lane = threadIdx.x & 7;
    if (node >= n) return;

    const int st = g_rowstart[node];
    const int cnt = g_cnt[node];

    float acc[8];
    #pragma unroll
    for (int j = 0; j < 8; j++) acc[j] = 0.0f;

    const uint4* __restrict__ hp = reinterpret_cast<const uint4*>(g_h16);

    int i = 0;
    for (; i + 4 <= cnt; i += 4) {
        unsigned e0 = g_epack[st + i + 0];
        unsigned e1 = g_epack[st + i + 1];
        unsigned e2 = g_epack[st + i + 2];
        unsigned e3 = g_epack[st + i + 3];
        uint4 h0 = hp[(size_t)(e0 & 0x1FFFFu) * 8 + lane];
        uint4 h1 = hp[(size_t)(e1 & 0x1FFFFu) * 8 + lane];
        uint4 h2 = hp[(size_t)(e2 & 0x1FFFFu) * 8 + lane];
        uint4 h3 = hp[(size_t)(e3 & 0x1FFFFu) * 8 + lane];
        float w0 = s_wl[e0 >> 17];
        float w1 = s_wl[e1 >> 17];
        float w2 = s_wl[e2 >> 17];
        float w3 = s_wl[e3 >> 17];
        const __nv_bfloat162* b0 = reinterpret_cast<const __nv_bfloat162*>(&h0);
        const __nv_bfloat162* b1 = reinterpret_cast<const __nv_bfloat162*>(&h1);
        const __nv_bfloat162* b2 = reinterpret_cast<const __nv_bfloat162*>(&h2);
        const __nv_bfloat162* b3 = reinterpret_cast<const __nv_bfloat162*>(&h3);
        #pragma unroll
        for (int j = 0; j < 4; j++) {
            float2 f0 = __bfloat1622float2(b0[j]);
            float2 f1 = __bfloat1622float2(b1[j]);
            float2 f2 = __bfloat1622float2(b2[j]);
            float2 f3 = __bfloat1622float2(b3[j]);
            acc[2 * j + 0] += f0.x * w0 + f1.x * w1 + f2.x * w2 + f3.x * w3;
            acc[2 * j + 1] += f0.y * w0 + f1.y * w1 + f2.y * w2 + f3.y * w3;
        }
    }
    for (; i < cnt; i++) {
        unsigned e0 = g_epack[st + i];
        uint4 h0 = hp[(size_t)(e0 & 0x1FFFFu) * 8 + lane];
        float w0 = s_wl[e0 >> 17];
        const __nv_bfloat162* b0 = reinterpret_cast<const __nv_bfloat162*>(&h0);
        #pragma unroll
        for (int j = 0; j < 4; j++) {
            float2 f0 = __bfloat1622float2(b0[j]);
            acc[2 * j + 0] += f0.x * w0;
            acc[2 * j + 1] += f0.y * w0;
        }
    }

    float4* op = reinterpret_cast<float4*>(out + (size_t)node * OUT_F + lane * 8);
    float4 a = op[0];
    float4 b = op[1];
    a.x += acc[0]; a.y += acc[1]; a.z += acc[2]; a.w += acc[3];
    b.x += acc[4]; b.y += acc[5]; b.z += acc[6]; b.w += acc[7];
    op[0] = a;
    op[1] = b;
}

// ---------------------------------------------------------------------------
// Launch
// ---------------------------------------------------------------------------
extern "C" void kernel_launch(void* const* d_in, const int* in_sizes, int n_in,
                              void* d_out, int out_size) {
    const float* feat        = (const float*)d_in[0];
    const float* edge_weight = (const float*)d_in[1];
    const float* weight      = (const float*)d_in[2];
    const float* bias        = (const float*)d_in[3];
    const int*   src         = (const int*)d_in[4];
    const int*   dst         = (const int*)d_in[5];
    const int*   efeat       = (const int*)d_in[6];
    float* out = (float*)d_out;

    int n = in_sizes[0] / IN_F;
    int E = in_sizes[4];
    int nb = (n + 2047) / 2048;
    int ne4 = (E + 3) / 4;

    zero_kernel<<<(n + 255) / 256, 256>>>(n);
    hist_kernel<<<(ne4 + 255) / 256, 256>>>(dst, efeat, edge_weight, E);
    scan_kernel<<<nb, 256>>>(n);
    scatter_kernel<<<(ne4 + 255) / 256, 256>>>(src, dst, efeat, E);

    gemm_kernel<<<(n + 63) / 64, 256>>>(feat, weight, bias, out, n);

    gather_kernel<<<(n + 31) / 32, 256>>>(out, edge_weight, n);
}

// round 17
// speedup vs baseline: 1.0158x; 1.0158x over previous
#include <cuda_runtime.h>
#include <cuda_bf16.h>
#include <cstdint>

#define IN_F 128
#define OUT_F 64
#define MAX_N 100000
#define MAX_E 1600000
#define ALPHAF 10.0f

// Scratch (allocation-free rule: __device__ globals)
__device__ int      g_cnt[MAX_N];        // per-dst in-degree counts
__device__ int      g_rowstart[MAX_N];   // CSR row offsets
__device__ int      g_cursor[MAX_N];     // scatter cursors
__device__ float    g_deg[MAX_N];        // sum of incoming edge weights
__device__ unsigned g_h16[(size_t)MAX_N * (OUT_F / 2)];  // h rows in bf16x2 words
__device__ unsigned g_epack[MAX_E];      // packed edge: src | (etype<<17)
// scan state: per-block aggregate + publish flag
__device__ volatile int g_scanflag[64];
__device__ volatile int g_scanagg[64];

// ---------------------------------------------------------------------------
// K1: zero counters + deg + scan flags
// ---------------------------------------------------------------------------
__global__ void zero_kernel(int n) {
    int i = blockIdx.x * blockDim.x + threadIdx.x;
    if (i < n) { g_cnt[i] = 0; g_deg[i] = 0.0f; }
    if (blockIdx.x == 0 && threadIdx.x < 64) g_scanflag[threadIdx.x] = 0;
}

// ---------------------------------------------------------------------------
// K2: histogram of dst + fused deg accumulation. 2 edges/thread.
// atomicAdd returns UNUSED -> REDG (no round-trip).
// ---------------------------------------------------------------------------
__global__ void hist_kernel(const int* __restrict__ dst,
                            const int* __restrict__ efeat,
                            const float* __restrict__ edge_weight,
                            int E) {
    int e = (blockIdx.x * blockDim.x + threadIdx.x) * 2;
    if (e + 1 < E) {
        int2 d2 = *reinterpret_cast<const int2*>(dst + e);
        int2 t2 = *reinterpret_cast<const int2*>(efeat + e);
        float w0 = __ldg(&edge_weight[t2.x - 1]) * ALPHAF;
        float w1 = __ldg(&edge_weight[t2.y - 1]) * ALPHAF;
        w0 = (w0 > 0.0f) ? w0 : 0.01f * w0;
        w1 = (w1 > 0.0f) ? w1 : 0.01f * w1;
        atomicAdd(&g_cnt[d2.x], 1);
        atomicAdd(&g_cnt[d2.y], 1);
        atomicAdd(&g_deg[d2.x], w0);
        atomicAdd(&g_deg[d2.y], w1);
    } else if (e < E) {
        int d = dst[e];
        float w = __ldg(&edge_weight[efeat[e] - 1]) * ALPHAF;
        w = (w > 0.0f) ? w : 0.01f * w;
        atomicAdd(&g_cnt[d], 1);
        atomicAdd(&g_deg[d], w);
    }
}

// ---------------------------------------------------------------------------
// K3: single-pass exclusive scan (parallel aggregate lookback)
// ---------------------------------------------------------------------------
__global__ __launch_bounds__(256) void scan_kernel(int n) {
    __shared__ int s[256];
    __shared__ int s_off;
    const int tid = threadIdx.x;
    const int b = blockIdx.x;
    const int base = b * 2048 + tid * 8;

    int v[8];
    int tsum = 0;
    #pragma unroll
    for (int j = 0; j < 8; j++) {
        int idx = base + j;
        int c = (idx < n) ? g_cnt[idx] : 0;
        v[j] = tsum;
        tsum += c;
    }
    s[tid] = tsum;
    __syncthreads();
    #pragma unroll
    for (int off = 1; off < 256; off <<= 1) {
        int t = 0;
        if (tid >= off) t = s[tid - off];
        __syncthreads();
        if (tid >= off) s[tid] += t;
        __syncthreads();
    }
    int texcl = s[tid] - tsum;
    int total = s[255];

    if (tid == 0) {
        s_off = 0;
        g_scanagg[b] = total;
        __threadfence();
        g_scanflag[b] = 1;
    }
    __syncthreads();

    if (tid < 32 && b > 0) {
        int run = 0;
        for (int base2 = 0; base2 < b; base2 += 32) {
            int p = base2 + tid;
            int val = 0;
            if (p < b) {
                while (g_scanflag[p] == 0) { }
                __threadfence();
                val = g_scanagg[p];
            }
            #pragma unroll
            for (int o = 16; o; o >>= 1)
                val += __shfl_down_sync(0xffffffffu, val, o);
            if (tid == 0) run += val;
        }
        if (tid == 0) s_off = run;
    }
    __syncthreads();
    int off = s_off;

    #pragma unroll
    for (int j = 0; j < 8; j++) {
        int idx = base + j;
        if (idx < n) {
            int r = off + texcl + v[j];
            g_rowstart[idx] = r;
            g_cursor[idx] = r;
        }
    }
}

// ---------------------------------------------------------------------------
// K4: scatter packed edges into CSR slots (cursor atomic). 2 edges/thread.
// ---------------------------------------------------------------------------
__global__ void scatter_kernel(const int* __restrict__ src,
                               const int* __restrict__ dst,
                               const int* __restrict__ efeat,
                               int E) {
    int e = (blockIdx.x * blockDim.x + threadIdx.x) * 2;
    if (e + 1 < E) {
        int2 s2 = *reinterpret_cast<const int2*>(src + e);
        int2 d2 = *reinterpret_cast<const int2*>(dst + e);
        int2 t2 = *reinterpret_cast<const int2*>(efeat + e);
        int p0 = atomicAdd(&g_cursor[d2.x], 1);
        int p1 = atomicAdd(&g_cursor[d2.y], 1);
        g_epack[p0] = (unsigned)s2.x | ((unsigned)(t2.x - 1) << 17);
        g_epack[p1] = (unsigned)s2.y | ((unsigned)(t2.y - 1) << 17);
    } else if (e < E) {
        int d = dst[e];
        int p = atomicAdd(&g_cursor[d], 1);
        g_epack[p] = (unsigned)src[e] | ((unsigned)(efeat[e] - 1) << 17);
    }
}

// ---------------------------------------------------------------------------
// K5: TF32 tensor-core GEMM with 3xTF32 compensation (~fp32 accuracy).
// ---------------------------------------------------------------------------
#define SA_STRIDE 132   // 64 rows
#define SB_STRIDE 72    // 128 rows

__device__ __forceinline__ unsigned f2tf32(float f) {
    unsigned r;
    asm("cvt.rna.tf32.f32 %0, %1;" : "=r"(r) : "f"(f));
    return r;
}

#define MMA_TF32(c, a0, a1, a2, a3, b0, b1)                                   \
    asm volatile("mma.sync.aligned.m16n8k8.row.col.f32.tf32.tf32.f32 "        \
                 "{%0,%1,%2,%3}, {%4,%5,%6,%7}, {%8,%9}, {%0,%1,%2,%3};"      \
                 : "+f"((c)[0]), "+f"((c)[1]), "+f"((c)[2]), "+f"((c)[3])     \
                 : "r"(a0), "r"(a1), "r"(a2), "r"(a3), "r"(b0), "r"(b1))

__global__ __launch_bounds__(256) void gemm_kernel(
    const float* __restrict__ feat,
    const float* __restrict__ weight,
    const float* __restrict__ bias,
    float* __restrict__ out,
    int n)
{
    __shared__ float sA[64 * SA_STRIDE];
    __shared__ float sB[IN_F * SB_STRIDE];

    const int tid = threadIdx.x;
    const int rowBase = blockIdx.x * 64;

    #pragma unroll
    for (int it = 0; it < 8; it++) {
        int idx = tid + it * 256;
        int r = idx >> 5;
        int c4 = idx & 31;
        float4 v = make_float4(0.f, 0.f, 0.f, 0.f);
        int gr = rowBase + r;
        if (gr < n)
            v = reinterpret_cast<const float4*>(feat)[(size_t)gr * (IN_F / 4) + c4];
        *reinterpret_cast<float4*>(&sA[r * SA_STRIDE + c4 * 4]) = v;
    }
    #pragma unroll
    for (int it = 0; it < 8; it++) {
        int idx = tid + it * 256;
        int r = idx >> 4;
        int c4 = idx & 15;
        float4 v = reinterpret_cast<const float4*>(weight)[(size_t)r * (OUT_F / 4) + c4];
        *reinterpret_cast<float4*>(&sB[r * SB_STRIDE + c4 * 4]) = v;
    }
    __syncthreads();

    const int wid = tid >> 5;
    const int lane = tid & 31;
    const int g = lane >> 2;
    const int t = lane & 3;
    const int m0 = (wid & 3) * 16;
    const int n0 = (wid >> 2) * 32;

    float c[4][4];
    #pragma unroll
    for (int nt = 0; nt < 4; nt++)
        #pragma unroll
        for (int j = 0; j < 4; j++) c[nt][j] = 0.0f;

    #pragma unroll
    for (int ks = 0; ks < IN_F / 8; ks++) {
        int k0 = ks * 8;
        float af0 = sA[(m0 + g)     * SA_STRIDE + k0 + t];
        float af1 = sA[(m0 + g + 8) * SA_STRIDE + k0 + t];
        float af2 = sA[(m0 + g)     * SA_STRIDE + k0 + t + 4];
        float af3 = sA[(m0 + g + 8) * SA_STRIDE + k0 + t + 4];
        unsigned ah0 = f2tf32(af0), ah1 = f2tf32(af1), ah2 = f2tf32(af2), ah3 = f2tf32(af3);
        unsigned al0 = f2tf32(af0 - __uint_as_float(ah0));
        unsigned al1 = f2tf32(af1 - __uint_as_float(ah1));
        unsigned al2 = f2tf32(af2 - __uint_as_float(ah2));
        unsigned al3 = f2tf32(af3 - __uint_as_float(ah3));

        #pragma unroll
        for (int nt = 0; nt < 4; nt++) {
            int nc = n0 + nt * 8 + g;
            float bf0 = sB[(k0 + t)     * SB_STRIDE + nc];
            float bf1 = sB[(k0 + t + 4) * SB_STRIDE + nc];
            unsigned bh0 = f2tf32(bf0), bh1 = f2tf32(bf1);
            unsigned bl0 = f2tf32(bf0 - __uint_as_float(bh0));
            unsigned bl1 = f2tf32(bf1 - __uint_as_float(bh1));
            MMA_TF32(c[nt], ah0, ah1, ah2, ah3, bh0, bh1);
            MMA_TF32(c[nt], al0, al1, al2, al3, bh0, bh1);
            MMA_TF32(c[nt], ah0, ah1, ah2, ah3, bl0, bl1);
        }
    }

    #pragma unroll
    for (int half = 0; half < 2; half++) {
        int gr = rowBase + m0 + g + half * 8;
        if (gr < n) {
            float d = g_deg[gr];
            float norm = 1.0f / fmaxf(d, 1.0f);
            #pragma unroll
            for (int nt = 0; nt < 4; nt++) {
                int col = n0 + nt * 8 + 2 * t;
                float cx = c[nt][half * 2 + 0];
                float cy = c[nt][half * 2 + 1];
                float2 bi = *reinterpret_cast<const float2*>(bias + col);
                float2 o = make_float2(cx + bi.x, cy + bi.y);
                *reinterpret_cast<float2*>(out + (size_t)gr * OUT_F + col) = o;
                __nv_bfloat162 p = __floats2bfloat162_rn(cx * norm, cy * norm);
                g_h16[(size_t)gr * (OUT_F / 2) + (col >> 1)] = *reinterpret_cast<unsigned*>(&p);
            }
        }
    }
}

// ---------------------------------------------------------------------------
// K6: pull-gather. 8 threads/node; uint4 per lane; unroll x8 (deep MLP) with
// out-RMW read hoisted above the loop to overlap its latency.
// ---------------------------------------------------------------------------
__global__ __launch_bounds__(256) void gather_kernel(
    float* __restrict__ out,
    const float* __restrict__ edge_weight,
    int n)
{
    __shared__ float s_wl[8];
    if (threadIdx.x < 8) {
        float w = edge_weight[threadIdx.x] * ALPHAF;
        s_wl[threadIdx.x] = (w > 0.0f) ? w : 0.01f * w;
    }
    __syncthreads();

    int node = blockIdx.x * 32 + (threadIdx.x >> 3);
    int lane = threadIdx.x & 7;
    if (node >= n) return;

    const int st = g_rowstart[node];
    const int cnt = g_cnt[node];

    // hoist the out RMW load: overlaps ~240cyc L2 latency with the edge loop
    float4* op = reinterpret_cast<float4*>(out + (size_t)node * OUT_F + lane * 8);
    float4 oa = op[0];
    float4 ob = op[1];

    float acc[8];
    #pragma unroll
    for (int j = 0; j < 8; j++) acc[j] = 0.0f;

    const uint4* __restrict__ hp = reinterpret_cast<const uint4*>(g_h16);
    const unsigned* __restrict__ ep = g_epack + st;

    int i = 0;
    // 8-wide body: 8 independent 128B row-gathers in flight per group
    for (; i + 8 <= cnt; i += 8) {
        unsigned e[8];
        #pragma unroll
        for (int u = 0; u < 8; u++) e[u] = ep[i + u];
        uint4 h[8];
        #pragma unroll
        for (int u = 0; u < 8; u++)
            h[u] = hp[(size_t)(e[u] & 0x1FFFFu) * 8 + lane];
        #pragma unroll
        for (int u = 0; u < 8; u++) {
            float w = s_wl[e[u] >> 17];
            const __nv_bfloat162* b = reinterpret_cast<const __nv_bfloat162*>(&h[u]);
            #pragma unroll
            for (int j = 0; j < 4; j++) {
                float2 f = __bfloat1622float2(b[j]);
                acc[2 * j + 0] += f.x * w;
                acc[2 * j + 1] += f.y * w;
            }
        }
    }
    // 2-wide tail
    for (; i + 2 <= cnt; i += 2) {
        unsigned e0 = ep[i], e1 = ep[i + 1];
        uint4 h0 = hp[(size_t)(e0 & 0x1FFFFu) * 8 + lane];
        uint4 h1 = hp[(size_t)(e1 & 0x1FFFFu) * 8 + lane];
        float w0 = s_wl[e0 >> 17];
        float w1 = s_wl[e1 >> 17];
        const __nv_bfloat162* b0 = reinterpret_cast<const __nv_bfloat162*>(&h0);
        const __nv_bfloat162* b1 = reinterpret_cast<const __nv_bfloat162*>(&h1);
        #pragma unroll
        for (int j = 0; j < 4; j++) {
            float2 f0 = __bfloat1622float2(b0[j]);
            float2 f1 = __bfloat1622float2(b1[j]);
            acc[2 * j + 0] += f0.x * w0 + f1.x * w1;
            acc[2 * j + 1] += f0.y * w0 + f1.y * w1;
        }
    }
    if (i < cnt) {
        unsigned e0 = ep[i];
        uint4 h0 = hp[(size_t)(e0 & 0x1FFFFu) * 8 + lane];
        float w0 = s_wl[e0 >> 17];
        const __nv_bfloat162* b0 = reinterpret_cast<const __nv_bfloat162*>(&h0);
        #pragma unroll
        for (int j = 0; j < 4; j++) {
            float2 f0 = __bfloat1622float2(b0[j]);
            acc[2 * j + 0] += f0.x * w0;
            acc[2 * j + 1] += f0.y * w0;
        }
    }

    oa.x += acc[0]; oa.y += acc[1]; oa.z += acc[2]; oa.w += acc[3];
    ob.x += acc[4]; ob.y += acc[5]; ob.z += acc[6]; ob.w += acc[7];
    op[0] = oa;
    op[1] = ob;
}

// ---------------------------------------------------------------------------
// Launch
// ---------------------------------------------------------------------------
extern "C" void kernel_launch(void* const* d_in, const int* in_sizes, int n_in,
                              void* d_out, int out_size) {
    const float* feat        = (const float*)d_in[0];
    const float* edge_weight = (const float*)d_in[1];
    const float* weight      = (const float*)d_in[2];
    const float* bias        = (const float*)d_in[3];
    const int*   src         = (const int*)d_in[4];
    const int*   dst         = (const int*)d_in[5];
    const int*   efeat       = (const int*)d_in[6];
    float* out = (float*)d_out;

    int n = in_sizes[0] / IN_F;
    int E = in_sizes[4];
    int nb = (n + 2047) / 2048;
    int ne2 = (E + 1) / 2;

    zero_kernel<<<(n + 255) / 256, 256>>>(n);
    hist_kernel<<<(ne2 + 255) / 256, 256>>>(dst, efeat, edge_weight, E);
    scan_kernel<<<nb, 256>>>(n);
    scatter_kernel<<<(ne2 + 255) / 256, 256>>>(src, dst, efeat, E);

    gemm_kernel<<<(n + 63) / 64, 256>>>(feat, weight, bias, out, n);

    gather_kernel<<<(n + 31) / 32, 256>>>(out, edge_weight, n);
}